// round 5
// baseline (speedup 1.0000x reference)
#include <cuda_runtime.h>
#include <cstdint>
#include <cstddef>

// MPS chain contraction, 32768 elements, 221 steps of 3x3 matrices.
// v_out = e0^T * M_1 * ... * M_221,  M_l = bias + sum_d x[l,d] * T[l,:,:,d]
//
// Round-5: segments split ACROSS blocks (6 segments of 37/37/37/37/37/36
// steps). Kernel 1: each block = one (segment, element-group); computes 3x3
// partial products for 256 f32x2 element-pairs, writes them to a global
// scratch. Kernel 2: combines 6 partials per pair.  This cuts per-block T
// smem 53KB -> 8.9KB and (with reg diet) allows 3 blocks/SM = 24 warps/SM.
// Bias==identity fast path folds the bias add into the P-accumulate fma.

typedef unsigned long long u64;

#define NSTEPS   221
#define NSEG     6
#define SEGLEN   37            // segs 0..4; seg 5 has 36
#define CH       5             // steps per chunk
#define NCH      8             // chunks (covers up to 40 steps)
#define PPB      256           // element pairs per block
#define EPB      512           // elements per block
#define BT       256           // threads per block
#define NEBLK    64            // element-group blocks (32768/512)
#define NBLK     (NSEG * NEBLK)   // 384
#define ESTRIDE  693           // floats per element
#define NPAIRS   16384

// Staging layout (bytes): row f (0..14) at f*ROWB, pair p at p*8.
// ROWB = 256*8 + 16 pad: word stride 518 = 6 mod 32 -> near conflict-free
// cp.async smem writes; 8B alignment kept for ld.shared.b64.
#define ROWB       2072
#define XBUF_BYTES (15 * ROWB)             // 31080
#define TSTRIDE    30                      // padded u64 per step
#define TSEG_U64   (SEGLEN * TSTRIDE)      // 1110
#define BIAS_OFF_U64 (2 * XBUF_BYTES / 8 + TSEG_U64)
#define SMEM_U64   (BIAS_OFF_U64 + 9)
#define SMEM_BYTES (SMEM_U64 * 8)          // 71112

__device__ u64 g_scratch[NSEG * 9 * NPAIRS];   // 7.08 MB partial matrices

__device__ __forceinline__ u64 f2fma(u64 a, u64 b, u64 c) {
    u64 d; asm("fma.rn.f32x2 %0, %1, %2, %3;" : "=l"(d) : "l"(a), "l"(b), "l"(c)); return d;
}
__device__ __forceinline__ u64 f2mul(u64 a, u64 b) {
    u64 d; asm("mul.rn.f32x2 %0, %1, %2;" : "=l"(d) : "l"(a), "l"(b)); return d;
}
__device__ __forceinline__ u64 dup2(float v) {
    u64 d; asm("mov.b64 %0, {%1, %1};" : "=l"(d) : "f"(v)); return d;
}
__device__ __forceinline__ void unpack2(u64 v, float& lo, float& hi) {
    asm("mov.b64 {%0, %1}, %2;" : "=f"(lo), "=f"(hi) : "l"(v));
}
__device__ __forceinline__ void lds2(u64& a, u64& b, uint32_t addr) {
    asm("ld.shared.v2.u64 {%0, %1}, [%2];" : "=l"(a), "=l"(b) : "r"(addr));
}
__device__ __forceinline__ u64 lds1(uint32_t addr) {
    u64 a; asm("ld.shared.b64 %0, [%1];" : "=l"(a) : "r"(addr)); return a;
}
__device__ __forceinline__ void cpa4(uint32_t dst, const float* src) {
    asm volatile("cp.async.ca.shared.global [%0], [%1], 4;" :: "r"(dst), "l"(src) : "memory");
}
__device__ __forceinline__ void cpcommit() {
    asm volatile("cp.async.commit_group;" ::: "memory");
}
template <int N> __device__ __forceinline__ void cpwait() {
    asm volatile("cp.async.wait_group %0;" :: "n"(N) : "memory");
}

extern __shared__ u64 smem_u64[];

// Stage chunk c: 512 elements x 15 floats (5 steps), starting at float
// offset 3*(lbase + 5c) within each element. i = eq*15 + j.
__device__ __forceinline__ void stage_chunk(const float* __restrict__ sb,
                                            uint32_t xb, int tid) {
    int j = tid % 15;
    int eq = tid / 15;
    #pragma unroll
    for (int k = 0; k < (EPB * 15) / BT; k++) {   // 30 iters
        const float* src = sb + (size_t)eq * ESTRIDE + j;
        uint32_t dst = xb + (uint32_t)(j * ROWB + (eq >> 1) * 8 + (eq & 1) * 4);
        cpa4(dst, src);
        j += 1; eq += 17;                 // +256 linear
        if (j >= 15) { j -= 15; eq += 1; }
    }
    cpcommit();
}

__global__ void __launch_bounds__(BT, 3)
mps_partial_kernel(const float* __restrict__ samples,
                   const float* __restrict__ T1,
                   const float* __restrict__ bias)
{
    const int tid  = threadIdx.x;
    const int seg  = blockIdx.x % NSEG;
    const int eblk = blockIdx.x / NSEG;
    const int e0   = eblk * EPB;
    const int lbase = SEGLEN * seg;
    const int len   = (seg == NSEG - 1) ? 36 : 37;

    uint32_t xbase0 = (uint32_t)__cvta_generic_to_shared(smem_u64);
    uint32_t xbase1 = xbase0 + XBUF_BYTES;
    uint32_t tbase  = xbase0 + 2 * XBUF_BYTES;
    u64* Tsh  = smem_u64 + (2 * XBUF_BYTES) / 8;
    u64* Bsh  = smem_u64 + BIAS_OFF_U64;

    // Stage this segment's T, duplicated (t,t), layout [l'][k(pad10)][j*3+d].
    for (int i = tid; i < len * 27; i += BT) {
        int l = i / 27, kd = i % 27;
        int k = kd / 9, jd = kd % 9;
        Tsh[l * TSTRIDE + k * 10 + jd] = dup2(T1[(lbase + l) * 27 + kd]);
    }
    if (tid < 9) Bsh[tid] = dup2(bias[tid]);

    // Uniform runtime check: bias == identity?
    bool ident = true;
    #pragma unroll
    for (int i = 0; i < 3; i++)
        #pragma unroll
        for (int j = 0; j < 3; j++)
            ident &= (bias[i * 3 + j] == ((i == j) ? 1.0f : 0.0f));

    const float* segbase = samples + (size_t)e0 * ESTRIDE + 3 * lbase;
    stage_chunk(segbase, xbase0, tid);

    // Partial product P starts as identity.
    u64 P[9];
    const u64 ONE2 = dup2(1.0f), ZERO2 = dup2(0.0f);
    #pragma unroll
    for (int j = 0; j < 9; j++) P[j] = (j % 4 == 0) ? ONE2 : ZERO2;

    const int p = tid;

    for (int c = 0; c < NCH; c++) {
        if (c + 1 < NCH) {
            stage_chunk(segbase + (c + 1) * (CH * 3),
                        ((c + 1) & 1) ? xbase1 : xbase0, tid);
            cpwait<1>();
        } else {
            cpwait<0>();
        }
        __syncthreads();

        uint32_t xaddr = ((c & 1) ? xbase1 : xbase0) + (uint32_t)(p * 8);
        const int nst = min(CH, len - c * CH);   // 5,5,...,then 2 (or 1)

        if (ident) {
            #pragma unroll
            for (int st = 0; st < CH; st++) {
                if (st >= nst) break;
                u64 X0 = lds1(xaddr + (st * 3 + 0) * ROWB);
                u64 X1 = lds1(xaddr + (st * 3 + 1) * ROWB);
                u64 X2 = lds1(xaddr + (st * 3 + 2) * ROWB);
                uint32_t taddr = tbase + (uint32_t)((c * CH + st) * (TSTRIDE * 8));

                u64 Pn[9];
                #pragma unroll
                for (int k = 0; k < 3; k++) {
                    u64 t0,t1,t2,t3,t4,t5,t6,t7,t8;
                    uint32_t ra = taddr + k * 80;
                    lds2(t0, t1, ra);
                    lds2(t2, t3, ra + 16);
                    lds2(t4, t5, ra + 32);
                    lds2(t6, t7, ra + 48);
                    t8 = lds1(ra + 64);
                    u64 S0 = f2fma(X2, t2, f2fma(X1, t1, f2mul(X0, t0)));
                    u64 S1 = f2fma(X2, t5, f2fma(X1, t4, f2mul(X0, t3)));
                    u64 S2 = f2fma(X2, t8, f2fma(X1, t7, f2mul(X0, t6)));
                    // bias == I: identity contribution folded into the init fma.
                    #pragma unroll
                    for (int i = 0; i < 3; i++) {
                        if (k == 0) {
                            Pn[i*3+0] = f2fma(P[i*3+0], S0, P[i*3+0]);
                            Pn[i*3+1] = f2fma(P[i*3+0], S1, P[i*3+1]);
                            Pn[i*3+2] = f2fma(P[i*3+0], S2, P[i*3+2]);
                        } else {
                            Pn[i*3+0] = f2fma(P[i*3+k], S0, Pn[i*3+0]);
                            Pn[i*3+1] = f2fma(P[i*3+k], S1, Pn[i*3+1]);
                            Pn[i*3+2] = f2fma(P[i*3+k], S2, Pn[i*3+2]);
                        }
                    }
                }
                #pragma unroll
                for (int j = 0; j < 9; j++) P[j] = Pn[j];
            }
        } else {
            // Generic bias path (correct for any bias; perf irrelevant here).
            #pragma unroll
            for (int st = 0; st < CH; st++) {
                if (st >= nst) break;
                u64 X0 = lds1(xaddr + (st * 3 + 0) * ROWB);
                u64 X1 = lds1(xaddr + (st * 3 + 1) * ROWB);
                u64 X2 = lds1(xaddr + (st * 3 + 2) * ROWB);
                uint32_t taddr = tbase + (uint32_t)((c * CH + st) * (TSTRIDE * 8));
                uint32_t baddr = (uint32_t)(tbase + (TSEG_U64) * 8);

                u64 Pn[9];
                #pragma unroll
                for (int k = 0; k < 3; k++) {
                    u64 t0,t1,t2,t3,t4,t5,t6,t7,t8;
                    uint32_t ra = taddr + k * 80;
                    lds2(t0, t1, ra);
                    lds2(t2, t3, ra + 16);
                    lds2(t4, t5, ra + 32);
                    lds2(t6, t7, ra + 48);
                    t8 = lds1(ra + 64);
                    u64 M0 = f2fma(X2, t2, f2fma(X1, t1, f2fma(X0, t0, lds1(baddr + (k*3+0)*8))));
                    u64 M1 = f2fma(X2, t5, f2fma(X1, t4, f2fma(X0, t3, lds1(baddr + (k*3+1)*8))));
                    u64 M2 = f2fma(X2, t8, f2fma(X1, t7, f2fma(X0, t6, lds1(baddr + (k*3+2)*8))));
                    #pragma unroll
                    for (int i = 0; i < 3; i++) {
                        if (k == 0) {
                            Pn[i*3+0] = f2mul(P[i*3+0], M0);
                            Pn[i*3+1] = f2mul(P[i*3+0], M1);
                            Pn[i*3+2] = f2mul(P[i*3+0], M2);
                        } else {
                            Pn[i*3+0] = f2fma(P[i*3+k], M0, Pn[i*3+0]);
                            Pn[i*3+1] = f2fma(P[i*3+k], M1, Pn[i*3+1]);
                            Pn[i*3+2] = f2fma(P[i*3+k], M2, Pn[i*3+2]);
                        }
                    }
                }
                #pragma unroll
                for (int j = 0; j < 9; j++) P[j] = Pn[j];
            }
        }
        __syncthreads();
    }

    // Store partial matrix, seg-major + coalesced over pairs.
    const int pp = eblk * PPB + p;
    #pragma unroll
    for (int j = 0; j < 9; j++)
        g_scratch[(seg * 9 + j) * NPAIRS + pp] = P[j];
}

__global__ void __launch_bounds__(BT)
mps_combine_kernel(float* __restrict__ out)
{
    const int pp = blockIdx.x * BT + threadIdx.x;

    // v = row 0 of P_seg0.
    u64 r0 = g_scratch[0 * NPAIRS + pp];
    u64 r1 = g_scratch[1 * NPAIRS + pp];
    u64 r2 = g_scratch[2 * NPAIRS + pp];

    #pragma unroll
    for (int s = 1; s < NSEG; s++) {
        const u64* m = g_scratch + (size_t)(s * 9) * NPAIRS + pp;
        u64 m0 = m[0*NPAIRS], m1 = m[1*NPAIRS], m2 = m[2*NPAIRS];
        u64 m3 = m[3*NPAIRS], m4 = m[4*NPAIRS], m5 = m[5*NPAIRS];
        u64 m6 = m[6*NPAIRS], m7 = m[7*NPAIRS], m8 = m[8*NPAIRS];
        u64 n0 = f2fma(r2, m6, f2fma(r1, m3, f2mul(r0, m0)));
        u64 n1 = f2fma(r2, m7, f2fma(r1, m4, f2mul(r0, m1)));
        u64 n2 = f2fma(r2, m8, f2fma(r1, m5, f2mul(r0, m2)));
        r0 = n0; r1 = n1; r2 = n2;
    }

    float a0,b0,a1,b1,a2,b2;
    unpack2(r0, a0, b0);
    unpack2(r1, a1, b1);
    unpack2(r2, a2, b2);
    float* oA = out + (size_t)pp * 6;
    oA[0] = a0; oA[1] = a1; oA[2] = a2;
    oA[3] = b0; oA[4] = b1; oA[5] = b2;
}

extern "C" void kernel_launch(void* const* d_in, const int* in_sizes, int n_in,
                              void* d_out, int out_size) {
    (void)in_sizes; (void)n_in; (void)out_size;
    const float* samples = (const float*)d_in[0];
    const float* tensors = (const float*)d_in[1];
    const float* bias    = (const float*)d_in[2];
    float* out = (float*)d_out;

    cudaFuncSetAttribute(mps_partial_kernel,
                         cudaFuncAttributeMaxDynamicSharedMemorySize, SMEM_BYTES);
    mps_partial_kernel<<<NBLK, BT, SMEM_BYTES>>>(samples, tensors, bias);
    mps_combine_kernel<<<NPAIRS / BT, BT>>>(out);
}

// round 6
// speedup vs baseline: 2.0656x; 2.0656x over previous
#include <cuda_runtime.h>
#include <cstdint>
#include <cstddef>

// MPS chain contraction, 32768 elements, 221 steps of 3x3 matrices.
// v_out = e0^T * M_1 * ... * M_221,  M_l = bias + sum_d x[l,d] * T[l,:,:,d]
//
// Round-6: scalar f32 (1 element/thread), 4 chain segments across blocks,
// DEPTH-3 cp.async pipeline (prefetch distance 2 chunks) to cover DRAM
// latency -- the 1-chunk-deep pipeline was the hidden stall in R1-R5.
// Seg-0 blocks propagate only the row vector (36 FMA/step); segs 1-3
// compute 3x3 partial products (54 FMA/step); a small second kernel
// combines. Bias==identity fast path folds bias into the accumulate FMA.

#define NSEG    4
#define BT      256
#define EPB     256            // elements per block (1 per thread)
#define NEBLK   128            // 32768 / 256
#define NBLK    (NSEG * NEBLK) // 512
#define CH      6              // steps per chunk
#define NCH     10             // chunks (covers 60 >= 56 steps)
#define ESTRIDE 693            // floats per element
#define NELEM   32768

// Staging layout (bytes): buffer b at b*CHUNKB, float row f (0..17) at
// f*ROWB, element e at e*4.  ROWB = 1028 -> word stride 257 == 1 (mod 32):
// near-conflict-free cp.async writes, fully conflict-free linear reads.
#define ROWB    1028
#define CHUNKB  18512          // 18*1028 = 18504, padded to 16B multiple
#define NBUF    3
#define TPAD    28             // floats per step in smem (27 + pad, 16B-aligned)
#define TBYTES  (56 * TPAD * 4)            // 6272
#define SMEM_BYTES (NBUF * CHUNKB + TBYTES)  // 55536 + 6272 = 61808

__device__ float g_vec[3 * NELEM];       // seg-0 vectors
__device__ float g_mat[3 * 9 * NELEM];   // seg 1..3 partial matrices

__device__ __forceinline__ float ldsf(uint32_t addr) {
    float v; asm("ld.shared.f32 %0, [%1];" : "=f"(v) : "r"(addr)); return v;
}
__device__ __forceinline__ void lds4(float& a, float& b, float& c, float& d, uint32_t addr) {
    asm("ld.shared.v4.f32 {%0,%1,%2,%3}, [%4];"
        : "=f"(a), "=f"(b), "=f"(c), "=f"(d) : "r"(addr));
}
__device__ __forceinline__ void cpa4(uint32_t dst, const float* src) {
    asm volatile("cp.async.ca.shared.global [%0], [%1], 4;" :: "r"(dst), "l"(src) : "memory");
}
__device__ __forceinline__ void cpcommit() {
    asm volatile("cp.async.commit_group;" ::: "memory");
}
template <int N> __device__ __forceinline__ void cpwait() {
    asm volatile("cp.async.wait_group %0;" :: "n"(N) : "memory");
}

extern __shared__ float smem_f[];

// Stage chunk c into buffer: 256 elements x 18 floats. i = eq*18 + j,
// lanes walk each element's contiguous 18-float run (global ~coalesced).
__device__ __forceinline__ void stage_chunk(const float* __restrict__ sb,
                                            uint32_t xb, int tid) {
    int j  = tid % 18;
    int eq = tid / 18;
    #pragma unroll
    for (int k = 0; k < 18; k++) {          // 256*18 / 256
        const float* src = sb + (size_t)eq * ESTRIDE + j;
        uint32_t dst = xb + (uint32_t)(j * ROWB + eq * 4);
        cpa4(dst, src);
        j += 4; eq += 14;                   // +256 linear
        if (j >= 18) { j -= 18; eq += 1; }
    }
    cpcommit();
}

__global__ void __launch_bounds__(BT, 3)
mps_partial_kernel(const float* __restrict__ samples,
                   const float* __restrict__ T1,
                   const float* __restrict__ bias)
{
    const int tid  = threadIdx.x;
    const int seg  = blockIdx.x & (NSEG - 1);
    const int eblk = blockIdx.x >> 2;
    const int e0   = eblk * EPB;
    const int lbase = (seg == 0) ? 0 : (55 * seg + 1);   // 0,56,111,166
    const int len   = (seg == 0) ? 56 : 55;

    uint32_t sbase = (uint32_t)__cvta_generic_to_shared(smem_f);
    uint32_t tbase = sbase + NBUF * CHUNKB;
    float* Tsh = smem_f + (NBUF * CHUNKB) / 4;

    // Stage this segment's T: [l][m] at l*TPAD + m (scalar, padded to 28).
    for (int i = tid; i < len * 27; i += BT) {
        int l = i / 27, m = i % 27;
        Tsh[l * TPAD + m] = T1[(lbase + l) * 27 + m];
    }

    float Bq[9];
    #pragma unroll
    for (int j = 0; j < 9; j++) Bq[j] = bias[j];
    bool ident = true;
    #pragma unroll
    for (int i = 0; i < 3; i++)
        #pragma unroll
        for (int j = 0; j < 3; j++)
            ident &= (Bq[i * 3 + j] == ((i == j) ? 1.0f : 0.0f));

    const float* segbase = samples + (size_t)e0 * ESTRIDE + 3 * lbase;

    // Depth-3 prologue: chunks 0,1,2 in flight before any compute.
    stage_chunk(segbase + 0 * (CH * 3), sbase + 0 * CHUNKB, tid);
    stage_chunk(segbase + 1 * (CH * 3), sbase + 1 * CHUNKB, tid);
    stage_chunk(segbase + 2 * (CH * 3), sbase + 2 * CHUNKB, tid);

    // State: seg 0 -> vector in P[0..2]; segs 1-3 -> matrix in P[0..8].
    float P[9];
    #pragma unroll
    for (int j = 0; j < 9; j++) P[j] = (j % 4 == 0) ? 1.0f : 0.0f;
    if (seg == 0) { P[1] = 0.0f; P[2] = 0.0f; }   // v = (1,0,0)

    for (int c = 0; c < NCH; c++) {
        if (c < NCH - 2)      cpwait<2>();   // chunk c landed, 2 still in flight
        else if (c == NCH-2)  cpwait<1>();
        else                  cpwait<0>();
        __syncthreads();

        uint32_t xaddr = sbase + (uint32_t)((c % NBUF) * CHUNKB + tid * 4);
        const int nst = min(CH, len - c * CH);    // 6,...,6, then 2 (or 1)

        #pragma unroll
        for (int st = 0; st < CH; st++) {
            if (st >= nst) break;
            float x0 = ldsf(xaddr + (st * 3 + 0) * ROWB);
            float x1 = ldsf(xaddr + (st * 3 + 1) * ROWB);
            float x2 = ldsf(xaddr + (st * 3 + 2) * ROWB);
            uint32_t ta = tbase + (uint32_t)((c * CH + st) * (TPAD * 4));
            float t[28];
            lds4(t[0],  t[1],  t[2],  t[3],  ta);
            lds4(t[4],  t[5],  t[6],  t[7],  ta + 16);
            lds4(t[8],  t[9],  t[10], t[11], ta + 32);
            lds4(t[12], t[13], t[14], t[15], ta + 48);
            lds4(t[16], t[17], t[18], t[19], ta + 64);
            lds4(t[20], t[21], t[22], t[23], ta + 80);
            lds4(t[24], t[25], t[26], t[27], ta + 96);

            if (ident) {
                // S[k][r] = sum_d x_d T[k][r][d]   (bias folded later)
                float S00 = fmaf(x2, t[2],  fmaf(x1, t[1],  x0 * t[0]));
                float S01 = fmaf(x2, t[5],  fmaf(x1, t[4],  x0 * t[3]));
                float S02 = fmaf(x2, t[8],  fmaf(x1, t[7],  x0 * t[6]));
                float S10 = fmaf(x2, t[11], fmaf(x1, t[10], x0 * t[9]));
                float S11 = fmaf(x2, t[14], fmaf(x1, t[13], x0 * t[12]));
                float S12 = fmaf(x2, t[17], fmaf(x1, t[16], x0 * t[15]));
                float S20 = fmaf(x2, t[20], fmaf(x1, t[19], x0 * t[18]));
                float S21 = fmaf(x2, t[23], fmaf(x1, t[22], x0 * t[21]));
                float S22 = fmaf(x2, t[26], fmaf(x1, t[25], x0 * t[24]));
                if (seg == 0) {
                    float a = P[0], b = P[1], cc = P[2];
                    P[0] = fmaf(cc, S20, fmaf(b, S10, fmaf(a, S00, a)));
                    P[1] = fmaf(cc, S21, fmaf(b, S11, fmaf(a, S01, b)));
                    P[2] = fmaf(cc, S22, fmaf(b, S12, fmaf(a, S02, cc)));
                } else {
                    #pragma unroll
                    for (int i = 0; i < 3; i++) {
                        float a = P[i*3+0], b = P[i*3+1], cc = P[i*3+2];
                        P[i*3+0] = fmaf(cc, S20, fmaf(b, S10, fmaf(a, S00, a)));
                        P[i*3+1] = fmaf(cc, S21, fmaf(b, S11, fmaf(a, S01, b)));
                        P[i*3+2] = fmaf(cc, S22, fmaf(b, S12, fmaf(a, S02, cc)));
                    }
                }
            } else {
                // Generic bias path (correct for any bias).
                float M00 = fmaf(x2, t[2],  fmaf(x1, t[1],  fmaf(x0, t[0],  Bq[0])));
                float M01 = fmaf(x2, t[5],  fmaf(x1, t[4],  fmaf(x0, t[3],  Bq[1])));
                float M02 = fmaf(x2, t[8],  fmaf(x1, t[7],  fmaf(x0, t[6],  Bq[2])));
                float M10 = fmaf(x2, t[11], fmaf(x1, t[10], fmaf(x0, t[9],  Bq[3])));
                float M11 = fmaf(x2, t[14], fmaf(x1, t[13], fmaf(x0, t[12], Bq[4])));
                float M12 = fmaf(x2, t[17], fmaf(x1, t[16], fmaf(x0, t[15], Bq[5])));
                float M20 = fmaf(x2, t[20], fmaf(x1, t[19], fmaf(x0, t[18], Bq[6])));
                float M21 = fmaf(x2, t[23], fmaf(x1, t[22], fmaf(x0, t[21], Bq[7])));
                float M22 = fmaf(x2, t[26], fmaf(x1, t[25], fmaf(x0, t[24], Bq[8])));
                if (seg == 0) {
                    float a = P[0], b = P[1], cc = P[2];
                    P[0] = fmaf(cc, M20, fmaf(b, M10, a * M00));
                    P[1] = fmaf(cc, M21, fmaf(b, M11, a * M01));
                    P[2] = fmaf(cc, M22, fmaf(b, M12, a * M02));
                } else {
                    #pragma unroll
                    for (int i = 0; i < 3; i++) {
                        float a = P[i*3+0], b = P[i*3+1], cc = P[i*3+2];
                        P[i*3+0] = fmaf(cc, M20, fmaf(b, M10, a * M00));
                        P[i*3+1] = fmaf(cc, M21, fmaf(b, M11, a * M01));
                        P[i*3+2] = fmaf(cc, M22, fmaf(b, M12, a * M02));
                    }
                }
            }
        }
        __syncthreads();
        if (c + NBUF < NCH)
            stage_chunk(segbase + (c + NBUF) * (CH * 3),
                        sbase + (uint32_t)((c % NBUF) * CHUNKB), tid);
    }

    const int ge = e0 + tid;
    if (seg == 0) {
        g_vec[0 * NELEM + ge] = P[0];
        g_vec[1 * NELEM + ge] = P[1];
        g_vec[2 * NELEM + ge] = P[2];
    } else {
        #pragma unroll
        for (int j = 0; j < 9; j++)
            g_mat[((seg - 1) * 9 + j) * NELEM + ge] = P[j];
    }
}

__global__ void __launch_bounds__(BT)
mps_combine_kernel(float* __restrict__ out)
{
    const int e = blockIdx.x * BT + threadIdx.x;
    float r0 = g_vec[0 * NELEM + e];
    float r1 = g_vec[1 * NELEM + e];
    float r2 = g_vec[2 * NELEM + e];
    #pragma unroll
    for (int s = 0; s < 3; s++) {
        const float* m = g_mat + (size_t)(s * 9) * NELEM + e;
        float m0 = m[0*NELEM], m1 = m[1*NELEM], m2 = m[2*NELEM];
        float m3 = m[3*NELEM], m4 = m[4*NELEM], m5 = m[5*NELEM];
        float m6 = m[6*NELEM], m7 = m[7*NELEM], m8 = m[8*NELEM];
        float n0 = fmaf(r2, m6, fmaf(r1, m3, r0 * m0));
        float n1 = fmaf(r2, m7, fmaf(r1, m4, r0 * m1));
        float n2 = fmaf(r2, m8, fmaf(r1, m5, r0 * m2));
        r0 = n0; r1 = n1; r2 = n2;
    }
    float* o = out + (size_t)e * 3;
    o[0] = r0; o[1] = r1; o[2] = r2;
}

extern "C" void kernel_launch(void* const* d_in, const int* in_sizes, int n_in,
                              void* d_out, int out_size) {
    (void)in_sizes; (void)n_in; (void)out_size;
    const float* samples = (const float*)d_in[0];
    const float* tensors = (const float*)d_in[1];
    const float* bias    = (const float*)d_in[2];
    float* out = (float*)d_out;

    cudaFuncSetAttribute(mps_partial_kernel,
                         cudaFuncAttributeMaxDynamicSharedMemorySize, SMEM_BYTES);
    mps_partial_kernel<<<NBLK, BT, SMEM_BYTES>>>(samples, tensors, bias);
    mps_combine_kernel<<<NELEM / BT, BT>>>(out);
}